// round 2
// baseline (speedup 1.0000x reference)
#include <cuda_runtime.h>
#include <cuda_bf16.h>
#include <math.h>

// ---------------------------------------------------------------------------
// RITS / BRITS-style recurrent imputation.
// B=512, T=128, D=128, H=128.
//
// Phase 1 (parallel precompute over B*T):
//   Gh   = exp(-relu(deltas @ Wth^T + bth))                [BT, H]
//   Gx   = exp(-relu(deltas @ Wtx^T + btx))                [BT, D]
//   beta = concat(Gx, m) @ Wwc + bwc                       [BT, D]
//   Gm   = m @ Wk[D:2D] + bl                               [BT, 4H]
//   denom[t] = sum_{b,d} m[:,t,:] + 1e-6
//   WthT/WtxT/WfrT transposes, Wg = [Wk[0:D]; Wr]          [256, 512]
//
// Phase 2 (sequential over T, batch-parallel): 128 CTAs x 4 rows each.
// ---------------------------------------------------------------------------

#define BT_TOT   65536   // B*T
#define T_STEPS  128
#define DD       128

// Scratch (device globals; no runtime allocation allowed)
__device__ float g_Gh[8388608];     // [BT, 128]
__device__ float g_Gx[8388608];     // [BT, 128]
__device__ float g_Beta[8388608];   // [BT, 128]
__device__ float g_Gm[33554432];    // [BT, 512]
__device__ float g_den[128];
__device__ float g_WthT[16384];
__device__ float g_WtxT[16384];
__device__ float g_WfrT[16384];
__device__ float g_Wg[131072];      // [256, 512]

__device__ __forceinline__ float sigmoidf_(float x) { return 1.0f / (1.0f + expf(-x)); }

// ---------------------------------------------------------------------------
// Small prep: transposes + fused gate weight
// ---------------------------------------------------------------------------
__global__ void prep_weights(const float* __restrict__ Wth, const float* __restrict__ Wtx,
                             const float* __restrict__ Wfr, const float* __restrict__ Wk,
                             const float* __restrict__ Wr,
                             float* __restrict__ WthT, float* __restrict__ WtxT,
                             float* __restrict__ WfrT, float* __restrict__ Wg)
{
    int idx = blockIdx.x * blockDim.x + threadIdx.x;
    if (idx < 16384) {
        int k = idx >> 7, j = idx & 127;
        WthT[idx] = Wth[j * 128 + k];
        WtxT[idx] = Wtx[j * 128 + k];
        WfrT[idx] = Wfr[j * 128 + k];
    }
    if (idx < 131072) {
        int k = idx >> 9, n = idx & 511;
        Wg[idx] = (k < 128) ? Wk[idx] : Wr[(k - 128) * 512 + n];
    }
}

// ---------------------------------------------------------------------------
// denom[t] = sum over (b, d) of masks[b, t, d] + eps
// ---------------------------------------------------------------------------
__global__ void denom_kernel(const float* __restrict__ masks, float* __restrict__ den)
{
    int t = blockIdx.x;
    float s = 0.0f;
    for (int i = threadIdx.x; i < 512 * 128; i += blockDim.x) {
        int b = i >> 7, d = i & 127;
        s += masks[((size_t)b * T_STEPS + t) * DD + d];
    }
    __shared__ float red[256];
    red[threadIdx.x] = s;
    __syncthreads();
    for (int off = 128; off > 0; off >>= 1) {
        if (threadIdx.x < off) red[threadIdx.x] += red[threadIdx.x + off];
        __syncthreads();
    }
    if (threadIdx.x == 0) den[t] = red[0] + 1e-6f;
}

// ---------------------------------------------------------------------------
// Tiled SGEMM: C[M,N] = epi(A[M,K] @ B[K,N] + bias)
// A split column-wise: k<128 -> A1, k>=128 -> A2 (both lda=128).
// BM=BN=64, BK=16, 256 threads, 4x4 micro-tile.
// epi==0: exp(-relu(v)), epi==1: v
// ---------------------------------------------------------------------------
__global__ void __launch_bounds__(256) sgemm_epi(
    const float* __restrict__ A1, const float* __restrict__ A2,
    const float* __restrict__ B, const float* __restrict__ bias,
    float* __restrict__ C, int N, int K, int epi)
{
    __shared__ float As[64][16];
    __shared__ float Bs[16][64];

    const int tid = threadIdx.x;
    const int bm = blockIdx.x * 64;
    const int bn = blockIdx.y * 64;
    const int tx = tid & 15;        // col group
    const int ty = tid >> 4;        // row group
    const int arow = tid >> 2;
    const int ak4 = (tid & 3) * 4;
    const int bk = tid >> 4;
    const int bn4 = (tid & 15) * 4;

    float acc[4][4];
#pragma unroll
    for (int i = 0; i < 4; i++)
#pragma unroll
        for (int jj = 0; jj < 4; jj++) acc[i][jj] = 0.0f;

    for (int k0 = 0; k0 < K; k0 += 16) {
        const float* Ab;
        int kloc;
        if (k0 < 128) { Ab = A1; kloc = k0; } else { Ab = A2; kloc = k0 - 128; }
        float4 av = *(const float4*)&Ab[(size_t)(bm + arow) * 128 + kloc + ak4];
        *(float4*)&As[arow][ak4] = av;
        float4 bv = *(const float4*)&B[(size_t)(k0 + bk) * N + bn + bn4];
        *(float4*)&Bs[bk][bn4] = bv;
        __syncthreads();
#pragma unroll
        for (int kk = 0; kk < 16; kk++) {
            float4 b4 = *(const float4*)&Bs[kk][tx * 4];
            float a0 = As[ty * 4 + 0][kk];
            float a1 = As[ty * 4 + 1][kk];
            float a2 = As[ty * 4 + 2][kk];
            float a3 = As[ty * 4 + 3][kk];
            acc[0][0] = fmaf(a0, b4.x, acc[0][0]); acc[0][1] = fmaf(a0, b4.y, acc[0][1]);
            acc[0][2] = fmaf(a0, b4.z, acc[0][2]); acc[0][3] = fmaf(a0, b4.w, acc[0][3]);
            acc[1][0] = fmaf(a1, b4.x, acc[1][0]); acc[1][1] = fmaf(a1, b4.y, acc[1][1]);
            acc[1][2] = fmaf(a1, b4.z, acc[1][2]); acc[1][3] = fmaf(a1, b4.w, acc[1][3]);
            acc[2][0] = fmaf(a2, b4.x, acc[2][0]); acc[2][1] = fmaf(a2, b4.y, acc[2][1]);
            acc[2][2] = fmaf(a2, b4.z, acc[2][2]); acc[2][3] = fmaf(a2, b4.w, acc[2][3]);
            acc[3][0] = fmaf(a3, b4.x, acc[3][0]); acc[3][1] = fmaf(a3, b4.y, acc[3][1]);
            acc[3][2] = fmaf(a3, b4.z, acc[3][2]); acc[3][3] = fmaf(a3, b4.w, acc[3][3]);
        }
        __syncthreads();
    }

#pragma unroll
    for (int i = 0; i < 4; i++) {
        float4 ov;
        float* o = (float*)&ov;
#pragma unroll
        for (int jj = 0; jj < 4; jj++) {
            float v = acc[i][jj] + bias[bn + tx * 4 + jj];
            if (epi == 0) v = expf(-fmaxf(v, 0.0f));
            o[jj] = v;
        }
        *(float4*)&C[(size_t)(bm + ty * 4 + i) * N + bn + tx * 4] = ov;
    }
}

// ---------------------------------------------------------------------------
// Sequential recurrence: 128 CTAs x 4 batch rows, 256 threads.
// Whr + WfrT cached in SMEM; Wg (256x512 fp32) streamed from L2 each step.
// ---------------------------------------------------------------------------
__global__ void __launch_bounds__(256, 1) seq_kernel(
    const float* __restrict__ values, const float* __restrict__ masks,
    const float* __restrict__ Whr, const float* __restrict__ bhr,
    const float* __restrict__ bfr,
    const float* __restrict__ Gh, const float* __restrict__ Beta,
    const float* __restrict__ Gm, const float* __restrict__ den,
    const float* __restrict__ Wd, const float* __restrict__ bd,
    const float* __restrict__ Wo, const float* __restrict__ bo,
    const float* __restrict__ WfrT, const float* __restrict__ Wg,
    float* __restrict__ out_pred, float* __restrict__ out_imp,
    float* __restrict__ out_loss)
{
    extern __shared__ float sm[];
    float* sWhr  = sm;                 // 16384
    float* sWfrT = sm + 16384;         // 16384
    float* sh    = sm + 32768;         // 512
    float* sc    = sh + 512;           // 512
    float* sxc   = sc + 512;           // 512
    float* scc   = sxc + 512;          // 512
    float* sg    = scc + 512;          // 2048 (gates / reductions)
    float* sbhr  = sg + 2048;          // 128
    float* sbfr  = sbhr + 128;         // 128

    const int tid = threadIdx.x;
    const int b0 = blockIdx.x * 4;

    for (int i = tid; i < 16384; i += 256) { sWhr[i] = Whr[i]; sWfrT[i] = WfrT[i]; }
    if (tid < 128) { sbhr[tid] = bhr[tid]; sbfr[tid] = bfr[tid]; }
    for (int i = tid; i < 512; i += 256) { sh[i] = 0.0f; sc[i] = 0.0f; }
    __syncthreads();

    const int j  = tid & 127;
    const int rp = tid >> 7;
    const int r0 = rp * 2, r1 = r0 + 1;
    const size_t row0 = (size_t)(b0 + r0) * T_STEPS;
    const size_t row1 = (size_t)(b0 + r1) * T_STEPS;
    const int n0 = tid * 2;

    float lsum0 = 0.0f, lsum1 = 0.0f;

    for (int t = 0; t < T_STEPS; t++) {
        const size_t bt0 = row0 + t, bt1 = row1 + t;

        // --- Phase A: load x, m; decay h ---
        float x0 = values[bt0 * DD + j], x1 = values[bt1 * DD + j];
        float m0 = masks[bt0 * DD + j],  m1 = masks[bt1 * DD + j];
        float h0 = sh[r0 * DD + j] * Gh[bt0 * DD + j];
        float h1 = sh[r1 * DD + j] * Gh[bt1 * DD + j];
        sh[r0 * DD + j] = h0;
        sh[r1 * DD + j] = h1;
        float rd = 1.0f / den[t];
        __syncthreads();

        // --- Phase B: x_hat = h @ Whr + bhr ---
        float a0 = sbhr[j], a1 = a0;
#pragma unroll 8
        for (int k = 0; k < 128; k += 2) {
            float w0 = sWhr[k * DD + j];
            float w1 = sWhr[(k + 1) * DD + j];
            float2 p = *(const float2*)&sh[r0 * DD + k];
            float2 q = *(const float2*)&sh[r1 * DD + k];
            a0 = fmaf(p.x, w0, a0); a0 = fmaf(p.y, w1, a0);
            a1 = fmaf(q.x, w0, a1); a1 = fmaf(q.y, w1, a1);
        }
        float xh0 = a0, xh1 = a1;
        float xc0 = m0 * x0 + (1.0f - m0) * xh0;
        float xc1 = m1 * x1 + (1.0f - m1) * xh1;
        sxc[r0 * DD + j] = xc0;
        sxc[r1 * DD + j] = xc1;
        lsum0 += fabsf(x0 - xh0) * m0 * rd;
        lsum1 += fabsf(x1 - xh1) * m1 * rd;
        __syncthreads();

        // --- Phase C: z_hat = x_c @ Wfr^T + bfr ---
        a0 = sbfr[j]; a1 = a0;
#pragma unroll 8
        for (int k = 0; k < 128; k += 2) {
            float w0 = sWfrT[k * DD + j];
            float w1 = sWfrT[(k + 1) * DD + j];
            float2 p = *(const float2*)&sxc[r0 * DD + k];
            float2 q = *(const float2*)&sxc[r1 * DD + k];
            a0 = fmaf(p.x, w0, a0); a0 = fmaf(p.y, w1, a0);
            a1 = fmaf(q.x, w0, a1); a1 = fmaf(q.y, w1, a1);
        }
        float zh0 = a0, zh1 = a1;
        lsum0 += fabsf(x0 - zh0) * m0 * rd;
        lsum1 += fabsf(x1 - zh1) * m1 * rd;

        // --- Phase D: c_hat / c_c / imputations ---
        float be0 = Beta[bt0 * DD + j], be1 = Beta[bt1 * DD + j];
        float ch0 = be0 * zh0 + (1.0f - be0) * xh0;
        float ch1 = be1 * zh1 + (1.0f - be1) * xh1;
        lsum0 += fabsf(x0 - ch0) * m0 * rd;
        lsum1 += fabsf(x1 - ch1) * m1 * rd;
        float cc0 = m0 * x0 + (1.0f - m0) * ch0;
        float cc1 = m1 * x1 + (1.0f - m1) * ch1;
        scc[r0 * DD + j] = cc0;
        scc[r1 * DD + j] = cc1;
        out_imp[bt0 * DD + j] = cc0;
        out_imp[bt1 * DD + j] = cc1;
        __syncthreads();

        // --- Phase E: gates = c_c @ Wg[0:128] + h @ Wg[128:256] + Gm ---
        float2 acc[4];
#pragma unroll
        for (int r = 0; r < 4; r++)
            acc[r] = *(const float2*)&Gm[((size_t)(b0 + r) * T_STEPS + t) * 512 + n0];

#pragma unroll 4
        for (int k = 0; k < 128; k += 2) {
            float2 w0 = *(const float2*)&Wg[(size_t)k * 512 + n0];
            float2 w1 = *(const float2*)&Wg[(size_t)(k + 1) * 512 + n0];
#pragma unroll
            for (int r = 0; r < 4; r++) {
                float2 v = *(const float2*)&scc[r * DD + k];
                acc[r].x = fmaf(v.x, w0.x, acc[r].x);
                acc[r].x = fmaf(v.y, w1.x, acc[r].x);
                acc[r].y = fmaf(v.x, w0.y, acc[r].y);
                acc[r].y = fmaf(v.y, w1.y, acc[r].y);
            }
        }
#pragma unroll 4
        for (int k = 0; k < 128; k += 2) {
            float2 w0 = *(const float2*)&Wg[(size_t)(128 + k) * 512 + n0];
            float2 w1 = *(const float2*)&Wg[(size_t)(129 + k) * 512 + n0];
#pragma unroll
            for (int r = 0; r < 4; r++) {
                float2 v = *(const float2*)&sh[r * DD + k];
                acc[r].x = fmaf(v.x, w0.x, acc[r].x);
                acc[r].x = fmaf(v.y, w1.x, acc[r].x);
                acc[r].y = fmaf(v.x, w0.y, acc[r].y);
                acc[r].y = fmaf(v.y, w1.y, acc[r].y);
            }
        }
#pragma unroll
        for (int r = 0; r < 4; r++)
            *(float2*)&sg[r * 512 + n0] = acc[r];
        __syncthreads();

        // --- Phase F: LSTM cell update (gate order i, f, g, o) ---
        {
            float gi = sg[r0 * 512 + j];
            float gf = sg[r0 * 512 + 128 + j];
            float gg = sg[r0 * 512 + 256 + j];
            float go = sg[r0 * 512 + 384 + j];
            float cn = sigmoidf_(gf) * sc[r0 * DD + j] + sigmoidf_(gi) * tanhf(gg);
            sc[r0 * DD + j] = cn;
            sh[r0 * DD + j] = sigmoidf_(go) * tanhf(cn);
        }
        {
            float gi = sg[r1 * 512 + j];
            float gf = sg[r1 * 512 + 128 + j];
            float gg = sg[r1 * 512 + 256 + j];
            float go = sg[r1 * 512 + 384 + j];
            float cn = sigmoidf_(gf) * sc[r1 * DD + j] + sigmoidf_(gi) * tanhf(gg);
            sc[r1 * DD + j] = cn;
            sh[r1 * DD + j] = sigmoidf_(go) * tanhf(cn);
        }
        __syncthreads();
    }

    // --- custom_loss: mean over T (per-step /denom already applied) ---
    sg[r0 * DD + j] = lsum0;
    sg[r1 * DD + j] = lsum1;
    __syncthreads();
    if (tid < 4) {
        float s = 0.0f;
        for (int k = 0; k < 128; k++) s += sg[tid * DD + k];
        out_loss[b0 + tid] = s * (1.0f / T_STEPS);
    }
    __syncthreads();

    // --- predictions = relu(h @ Wd + bd) @ Wo + bo ---
    float a0 = bd[j], a1 = bd[j];
    for (int k = 0; k < 128; k++) {
        float w = Wd[k * DD + j];
        a0 = fmaf(sh[r0 * DD + k], w, a0);
        a1 = fmaf(sh[r1 * DD + k], w, a1);
    }
    float wo = Wo[j];
    float p0 = fmaxf(a0, 0.0f) * wo;
    float p1 = fmaxf(a1, 0.0f) * wo;
    sg[r0 * DD + j] = p0;
    sg[r1 * DD + j] = p1;
    __syncthreads();
    if (tid < 4) {
        float s = 0.0f;
        for (int k = 0; k < 128; k++) s += sg[tid * DD + k];
        out_pred[b0 + tid] = s + bo[0];
    }
}

// ---------------------------------------------------------------------------
extern "C" void kernel_launch(void* const* d_in, const int* in_sizes, int n_in,
                              void* d_out, int out_size)
{
    const float* values = (const float*)d_in[0];
    const float* masks  = (const float*)d_in[1];
    const float* deltas = (const float*)d_in[2];
    const float* Wth    = (const float*)d_in[3];
    const float* bth    = (const float*)d_in[4];
    const float* Wtx    = (const float*)d_in[5];
    const float* btx    = (const float*)d_in[6];
    const float* Whr    = (const float*)d_in[7];
    const float* bhr    = (const float*)d_in[8];
    const float* Wfr    = (const float*)d_in[9];
    const float* bfr    = (const float*)d_in[10];
    const float* Wwc    = (const float*)d_in[11];
    const float* bwc    = (const float*)d_in[12];
    const float* Wk     = (const float*)d_in[13];
    const float* Wr     = (const float*)d_in[14];
    const float* bl     = (const float*)d_in[15];
    const float* Wd     = (const float*)d_in[16];
    const float* bd     = (const float*)d_in[17];
    const float* Wo     = (const float*)d_in[18];
    const float* bo     = (const float*)d_in[19];

    float *pGh, *pGx, *pBeta, *pGm, *pDen, *pWthT, *pWtxT, *pWfrT, *pWg;
    cudaGetSymbolAddress((void**)&pGh,   g_Gh);
    cudaGetSymbolAddress((void**)&pGx,   g_Gx);
    cudaGetSymbolAddress((void**)&pBeta, g_Beta);
    cudaGetSymbolAddress((void**)&pGm,   g_Gm);
    cudaGetSymbolAddress((void**)&pDen,  g_den);
    cudaGetSymbolAddress((void**)&pWthT, g_WthT);
    cudaGetSymbolAddress((void**)&pWtxT, g_WtxT);
    cudaGetSymbolAddress((void**)&pWfrT, g_WfrT);
    cudaGetSymbolAddress((void**)&pWg,   g_Wg);

    prep_weights<<<512, 256>>>(Wth, Wtx, Wfr, Wk, Wr, pWthT, pWtxT, pWfrT, pWg);
    denom_kernel<<<128, 256>>>(masks, pDen);

    dim3 g1(1024, 2);
    sgemm_epi<<<g1, 256>>>(deltas, nullptr, pWthT, bth, pGh, 128, 128, 0);
    sgemm_epi<<<g1, 256>>>(deltas, nullptr, pWtxT, btx, pGx, 128, 128, 0);
    sgemm_epi<<<g1, 256>>>(pGx, masks, Wwc, bwc, pBeta, 128, 256, 1);
    dim3 g2(1024, 8);
    sgemm_epi<<<g2, 256>>>(masks, nullptr, Wk + 128 * 512, bl, pGm, 512, 128, 1);

    float* out = (float*)d_out;
    const size_t SMEM = (size_t)(16384 + 16384 + 512 * 4 + 2048 + 256) * sizeof(float); // 148480 B
    cudaFuncSetAttribute(seq_kernel, cudaFuncAttributeMaxDynamicSharedMemorySize, (int)SMEM);
    seq_kernel<<<128, 256, SMEM>>>(values, masks, Whr, bhr, bfr,
                                   pGh, pBeta, pGm, pDen,
                                   Wd, bd, Wo, bo, pWfrT, pWg,
                                   out,                     // predictions [512]
                                   out + 512,               // imputations [512*128*128]
                                   out + 512 + 8388608);    // custom_loss [512]
}

// round 3
// speedup vs baseline: 1.0828x; 1.0828x over previous
#include <cuda_runtime.h>
#include <cuda_bf16.h>
#include <math.h>

// ---------------------------------------------------------------------------
// RITS / BRITS-style recurrent imputation. B=512, T=128, D=H=128.
//
// Phase 1 (parallel precompute over B*T):
//   Gh   = exp(-relu(deltas @ Wth^T))      [BT,128]
//   Gx   = exp(-relu(deltas @ Wtx^T))      [BT,128]
//   beta = [Gx, m] @ Wwc + bwc             [BT,128]
//   Gm   = m @ Wk[D:2D] + bl               [BT,512]
//   denom[t], weight repacks (k-pair interleaved for packed f32x2 math)
//
// Phase 2 (sequential over T): 128 CTAs x 4 batch rows x 256 threads.
// All inner products use fma.rn.f32x2 (FFMA2) — exact fp32, 2 MACs/instr.
// ---------------------------------------------------------------------------

#define T_STEPS  128
#define DD       128

typedef unsigned long long ull;

// Scratch (device globals; no runtime allocation allowed)
__device__ __align__(16) float g_Gh[8388608];     // [BT, 128]
__device__ __align__(16) float g_Gx[8388608];     // [BT, 128]
__device__ __align__(16) float g_Beta[8388608];   // [BT, 128]
__device__ __align__(16) float g_Gm[33554432];    // [BT, 512]
__device__ __align__(16) float g_den[128];
__device__ __align__(16) float g_WthT[16384];
__device__ __align__(16) float g_WtxT[16384];
__device__ __align__(16) float g_WhrP[16384];     // [64 kp][128 j][2 e]
__device__ __align__(16) float g_WfrP[16384];     // [64 kp][128 j][2 e]
__device__ __align__(16) float g_WgP[131072];     // [128 kp][512 n][2 e]

__device__ __forceinline__ float sigmoidf_(float x) { return 1.0f / (1.0f + expf(-x)); }

__device__ __forceinline__ void ffma2(ull& d, ull a, ull b) {
    asm("fma.rn.f32x2 %0, %1, %2, %0;" : "+l"(d) : "l"(a), "l"(b));
}
__device__ __forceinline__ ull packf2(float a, float b) {
    ull u; asm("mov.b64 %0, {%1, %2};" : "=l"(u) : "f"(a), "f"(b)); return u;
}
__device__ __forceinline__ float hsum2(ull u) {
    float x, y; asm("mov.b64 {%0, %1}, %2;" : "=f"(x), "=f"(y) : "l"(u));
    return x + y;
}

// ---------------------------------------------------------------------------
// Prep: transposes + k-pair-interleaved repacks
// ---------------------------------------------------------------------------
__global__ void prep_weights(const float* __restrict__ Wth, const float* __restrict__ Wtx,
                             const float* __restrict__ Whr, const float* __restrict__ Wfr,
                             const float* __restrict__ Wk,  const float* __restrict__ Wr,
                             float* __restrict__ WthT, float* __restrict__ WtxT,
                             float* __restrict__ WhrP, float* __restrict__ WfrP,
                             float* __restrict__ WgP)
{
    int idx = blockIdx.x * blockDim.x + threadIdx.x;
    if (idx < 16384) {
        int k = idx >> 7, j = idx & 127;
        WthT[idx] = Wth[j * 128 + k];
        WtxT[idx] = Wtx[j * 128 + k];
        // pair-interleaved: WhrP[kp*256 + j*2 + e] = Whr[(2kp+e)*128 + j]
        int kp = idx >> 8, rem = idx & 255, jj = rem >> 1, e = rem & 1;
        WhrP[idx] = Whr[(2 * kp + e) * 128 + jj];
        WfrP[idx] = Wfr[jj * 128 + 2 * kp + e];       // z_hat uses Wfr[j][k]
    }
    if (idx < 131072) {
        // WgP[kp*1024 + n*2 + e] = Wg[(2kp+e)*512 + n], Wg = [Wk_top; Wr]
        int kp = idx >> 10, rem = idx & 1023, n = rem >> 1, e = rem & 1;
        int k = 2 * kp + e;
        WgP[idx] = (k < 128) ? Wk[k * 512 + n] : Wr[(k - 128) * 512 + n];
    }
}

// ---------------------------------------------------------------------------
__global__ void denom_kernel(const float* __restrict__ masks, float* __restrict__ den)
{
    int t = blockIdx.x;
    float s = 0.0f;
    for (int i = threadIdx.x; i < 512 * 128; i += blockDim.x) {
        int b = i >> 7, d = i & 127;
        s += masks[((size_t)b * T_STEPS + t) * DD + d];
    }
    __shared__ float red[256];
    red[threadIdx.x] = s;
    __syncthreads();
    for (int off = 128; off > 0; off >>= 1) {
        if (threadIdx.x < off) red[threadIdx.x] += red[threadIdx.x + off];
        __syncthreads();
    }
    if (threadIdx.x == 0) den[t] = red[0] + 1e-6f;
}

// ---------------------------------------------------------------------------
// Tiled SGEMM (precompute): C = epi(A @ B + bias). Unchanged from R2.
// ---------------------------------------------------------------------------
__global__ void __launch_bounds__(256) sgemm_epi(
    const float* __restrict__ A1, const float* __restrict__ A2,
    const float* __restrict__ B, const float* __restrict__ bias,
    float* __restrict__ C, int N, int K, int epi)
{
    __shared__ float As[64][16];
    __shared__ float Bs[16][64];

    const int tid = threadIdx.x;
    const int bm = blockIdx.x * 64;
    const int bn = blockIdx.y * 64;
    const int tx = tid & 15;
    const int ty = tid >> 4;
    const int arow = tid >> 2;
    const int ak4 = (tid & 3) * 4;
    const int bk = tid >> 4;
    const int bn4 = (tid & 15) * 4;

    float acc[4][4];
#pragma unroll
    for (int i = 0; i < 4; i++)
#pragma unroll
        for (int jj = 0; jj < 4; jj++) acc[i][jj] = 0.0f;

    for (int k0 = 0; k0 < K; k0 += 16) {
        const float* Ab;
        int kloc;
        if (k0 < 128) { Ab = A1; kloc = k0; } else { Ab = A2; kloc = k0 - 128; }
        float4 av = *(const float4*)&Ab[(size_t)(bm + arow) * 128 + kloc + ak4];
        *(float4*)&As[arow][ak4] = av;
        float4 bv = *(const float4*)&B[(size_t)(k0 + bk) * N + bn + bn4];
        *(float4*)&Bs[bk][bn4] = bv;
        __syncthreads();
#pragma unroll
        for (int kk = 0; kk < 16; kk++) {
            float4 b4 = *(const float4*)&Bs[kk][tx * 4];
            float a0 = As[ty * 4 + 0][kk];
            float a1 = As[ty * 4 + 1][kk];
            float a2 = As[ty * 4 + 2][kk];
            float a3 = As[ty * 4 + 3][kk];
            acc[0][0] = fmaf(a0, b4.x, acc[0][0]); acc[0][1] = fmaf(a0, b4.y, acc[0][1]);
            acc[0][2] = fmaf(a0, b4.z, acc[0][2]); acc[0][3] = fmaf(a0, b4.w, acc[0][3]);
            acc[1][0] = fmaf(a1, b4.x, acc[1][0]); acc[1][1] = fmaf(a1, b4.y, acc[1][1]);
            acc[1][2] = fmaf(a1, b4.z, acc[1][2]); acc[1][3] = fmaf(a1, b4.w, acc[1][3]);
            acc[2][0] = fmaf(a2, b4.x, acc[2][0]); acc[2][1] = fmaf(a2, b4.y, acc[2][1]);
            acc[2][2] = fmaf(a2, b4.z, acc[2][2]); acc[2][3] = fmaf(a2, b4.w, acc[2][3]);
            acc[3][0] = fmaf(a3, b4.x, acc[3][0]); acc[3][1] = fmaf(a3, b4.y, acc[3][1]);
            acc[3][2] = fmaf(a3, b4.z, acc[3][2]); acc[3][3] = fmaf(a3, b4.w, acc[3][3]);
        }
        __syncthreads();
    }

#pragma unroll
    for (int i = 0; i < 4; i++) {
        float4 ov;
        float* o = (float*)&ov;
#pragma unroll
        for (int jj = 0; jj < 4; jj++) {
            float v = acc[i][jj] + bias[bn + tx * 4 + jj];
            if (epi == 0) v = expf(-fmaxf(v, 0.0f));
            o[jj] = v;
        }
        *(float4*)&C[(size_t)(bm + ty * 4 + i) * N + bn + tx * 4] = ov;
    }
}

// ---------------------------------------------------------------------------
// Sequential recurrence: 128 CTAs x 4 batch rows, 256 threads.
// Packed-k FFMA2 everywhere. WgP streamed from L2 via coalesced LDG.128.
// ---------------------------------------------------------------------------
__global__ void __launch_bounds__(256, 1) seq_kernel(
    const float* __restrict__ values, const float* __restrict__ masks,
    const float* __restrict__ WhrP_g, const float* __restrict__ bhr,
    const float* __restrict__ bfr,    const float* __restrict__ WfrP_g,
    const float* __restrict__ Gh,     const float* __restrict__ Beta,
    const float* __restrict__ Gm,     const float* __restrict__ den,
    const float* __restrict__ Wd,     const float* __restrict__ bd,
    const float* __restrict__ Wo,     const float* __restrict__ bo,
    const float* __restrict__ WgP,
    float* __restrict__ out_pred, float* __restrict__ out_imp,
    float* __restrict__ out_loss)
{
    extern __shared__ float sm[];
    float* sWhrP = sm;                 // 16384
    float* sWfrP = sm + 16384;         // 16384
    float* sh    = sm + 32768;         // 512
    float* sc    = sh + 512;           // 512
    float* sxc   = sc + 512;           // 512
    float* scc   = sxc + 512;          // 512
    float* sg    = scc + 512;          // 2048
    float* sbhr  = sg + 2048;          // 128
    float* sbfr  = sbhr + 128;         // 128

    const int tid = threadIdx.x;
    const int b0 = blockIdx.x * 4;

    for (int i = tid; i < 16384; i += 256) { sWhrP[i] = WhrP_g[i]; sWfrP[i] = WfrP_g[i]; }
    if (tid < 128) { sbhr[tid] = bhr[tid]; sbfr[tid] = bfr[tid]; }
    for (int i = tid; i < 512; i += 256) { sh[i] = 0.0f; sc[i] = 0.0f; }
    __syncthreads();

    const int j  = tid & 127;
    const int rp = tid >> 7;
    const int r0 = rp * 2, r1 = r0 + 1;
    const size_t row0 = (size_t)(b0 + r0) * T_STEPS;
    const size_t row1 = (size_t)(b0 + r1) * T_STEPS;
    const int n0 = tid * 2;

    float lsum0 = 0.0f, lsum1 = 0.0f;

    // Prefetch t=0 per-row operands
    float cx0 = values[row0 * DD + j], cx1 = values[row1 * DD + j];
    float cm0 = masks[row0 * DD + j],  cm1 = masks[row1 * DD + j];
    float cg0 = Gh[row0 * DD + j],     cg1 = Gh[row1 * DD + j];
    float cb0 = Beta[row0 * DD + j],   cb1 = Beta[row1 * DD + j];
    float cden = den[0];

    for (int t = 0; t < T_STEPS; t++) {
        const size_t bt0 = row0 + t, bt1 = row1 + t;

        // --- Phase A: decay h ---
        float x0 = cx0, x1 = cx1, m0 = cm0, m1 = cm1;
        float h0 = sh[r0 * DD + j] * cg0;
        float h1 = sh[r1 * DD + j] * cg1;
        sh[r0 * DD + j] = h0;
        sh[r1 * DD + j] = h1;
        float rd = 1.0f / cden;
        float be0 = cb0, be1 = cb1;
        __syncthreads();                                   // S1

        // --- Prefetch t+1 per-row operands + Gm(t) (overlaps B/C/E) ---
        {
            int tn = (t + 1 < T_STEPS) ? (t + 1) : (T_STEPS - 1);
            size_t nb0 = row0 + tn, nb1 = row1 + tn;
            cx0 = values[nb0 * DD + j]; cx1 = values[nb1 * DD + j];
            cm0 = masks[nb0 * DD + j];  cm1 = masks[nb1 * DD + j];
            cg0 = Gh[nb0 * DD + j];     cg1 = Gh[nb1 * DD + j];
            cb0 = Beta[nb0 * DD + j];   cb1 = Beta[nb1 * DD + j];
            cden = den[tn];
        }
        ull acc[4][2];
#pragma unroll
        for (int r = 0; r < 4; r++) {
            float2 gm = *(const float2*)&Gm[((size_t)(b0 + r) * T_STEPS + t) * 512 + n0];
            acc[r][0] = packf2(gm.x, 0.0f);
            acc[r][1] = packf2(gm.y, 0.0f);
        }

        // --- Phase B: x_hat = h @ Whr + bhr (packed-k FFMA2) ---
        ull a0 = packf2(sbhr[j], 0.0f), a1 = a0;
#pragma unroll 8
        for (int kp = 0; kp < 64; kp++) {
            ull w  = *(const ull*)&sWhrP[kp * 256 + 2 * j];
            ull v0 = *(const ull*)&sh[r0 * DD + 2 * kp];
            ull v1 = *(const ull*)&sh[r1 * DD + 2 * kp];
            ffma2(a0, v0, w);
            ffma2(a1, v1, w);
        }
        float xh0 = hsum2(a0), xh1 = hsum2(a1);
        float xc0 = m0 * x0 + (1.0f - m0) * xh0;
        float xc1 = m1 * x1 + (1.0f - m1) * xh1;
        sxc[r0 * DD + j] = xc0;
        sxc[r1 * DD + j] = xc1;
        lsum0 += fabsf(x0 - xh0) * m0 * rd;
        lsum1 += fabsf(x1 - xh1) * m1 * rd;
        __syncthreads();                                   // S2

        // --- Phase C: z_hat = x_c @ Wfr^T + bfr ---
        a0 = packf2(sbfr[j], 0.0f); a1 = a0;
#pragma unroll 8
        for (int kp = 0; kp < 64; kp++) {
            ull w  = *(const ull*)&sWfrP[kp * 256 + 2 * j];
            ull v0 = *(const ull*)&sxc[r0 * DD + 2 * kp];
            ull v1 = *(const ull*)&sxc[r1 * DD + 2 * kp];
            ffma2(a0, v0, w);
            ffma2(a1, v1, w);
        }
        float zh0 = hsum2(a0), zh1 = hsum2(a1);
        lsum0 += fabsf(x0 - zh0) * m0 * rd;
        lsum1 += fabsf(x1 - zh1) * m1 * rd;

        // --- Phase D: c_hat / c_c / imputations ---
        float ch0 = be0 * zh0 + (1.0f - be0) * xh0;
        float ch1 = be1 * zh1 + (1.0f - be1) * xh1;
        lsum0 += fabsf(x0 - ch0) * m0 * rd;
        lsum1 += fabsf(x1 - ch1) * m1 * rd;
        float cc0 = m0 * x0 + (1.0f - m0) * ch0;
        float cc1 = m1 * x1 + (1.0f - m1) * ch1;
        scc[r0 * DD + j] = cc0;
        scc[r1 * DD + j] = cc1;
        out_imp[bt0 * DD + j] = cc0;
        out_imp[bt1 * DD + j] = cc1;
        __syncthreads();                                   // S3

        // --- Phase E: gates = c_c @ Wg[0:128] + h @ Wg[128:256] + Gm ---
        // WgP: [128 kp][512 n][2], thread reads 16B (both its cols' k-pair).
        {
            const ulonglong2* wp = (const ulonglong2*)(WgP + (size_t)n0 * 2);
#pragma unroll 4
            for (int kp = 0; kp < 64; kp++) {
                ulonglong2 w = wp[kp * 256];               // kp*1024 floats / 4
                ull v0 = *(const ull*)&scc[0 * DD + 2 * kp];
                ull v1 = *(const ull*)&scc[1 * DD + 2 * kp];
                ull v2 = *(const ull*)&scc[2 * DD + 2 * kp];
                ull v3 = *(const ull*)&scc[3 * DD + 2 * kp];
                ffma2(acc[0][0], v0, w.x); ffma2(acc[0][1], v0, w.y);
                ffma2(acc[1][0], v1, w.x); ffma2(acc[1][1], v1, w.y);
                ffma2(acc[2][0], v2, w.x); ffma2(acc[2][1], v2, w.y);
                ffma2(acc[3][0], v3, w.x); ffma2(acc[3][1], v3, w.y);
            }
#pragma unroll 4
            for (int kp = 64; kp < 128; kp++) {
                ulonglong2 w = wp[kp * 256];
                int ko = 2 * kp - 128;
                ull v0 = *(const ull*)&sh[0 * DD + ko];
                ull v1 = *(const ull*)&sh[1 * DD + ko];
                ull v2 = *(const ull*)&sh[2 * DD + ko];
                ull v3 = *(const ull*)&sh[3 * DD + ko];
                ffma2(acc[0][0], v0, w.x); ffma2(acc[0][1], v0, w.y);
                ffma2(acc[1][0], v1, w.x); ffma2(acc[1][1], v1, w.y);
                ffma2(acc[2][0], v2, w.x); ffma2(acc[2][1], v2, w.y);
                ffma2(acc[3][0], v3, w.x); ffma2(acc[3][1], v3, w.y);
            }
#pragma unroll
            for (int r = 0; r < 4; r++) {
                float2 g2;
                g2.x = hsum2(acc[r][0]);
                g2.y = hsum2(acc[r][1]);
                *(float2*)&sg[r * 512 + n0] = g2;
            }
        }
        __syncthreads();                                   // S4

        // --- Phase F: LSTM cell update (i, f, g, o) ---
        {
            float gi = sg[r0 * 512 + j];
            float gf = sg[r0 * 512 + 128 + j];
            float gg = sg[r0 * 512 + 256 + j];
            float go = sg[r0 * 512 + 384 + j];
            float cn = sigmoidf_(gf) * sc[r0 * DD + j] + sigmoidf_(gi) * tanhf(gg);
            sc[r0 * DD + j] = cn;
            sh[r0 * DD + j] = sigmoidf_(go) * tanhf(cn);
        }
        {
            float gi = sg[r1 * 512 + j];
            float gf = sg[r1 * 512 + 128 + j];
            float gg = sg[r1 * 512 + 256 + j];
            float go = sg[r1 * 512 + 384 + j];
            float cn = sigmoidf_(gf) * sc[r1 * DD + j] + sigmoidf_(gi) * tanhf(gg);
            sc[r1 * DD + j] = cn;
            sh[r1 * DD + j] = sigmoidf_(go) * tanhf(cn);
        }
        // no sync needed: next Phase A touches only this thread's own slots,
        // and S1 orders everything before Phase B reads.
    }

    __syncthreads();

    // --- custom_loss ---
    sg[r0 * DD + j] = lsum0;
    sg[r1 * DD + j] = lsum1;
    __syncthreads();
    if (tid < 4) {
        float s = 0.0f;
        for (int k = 0; k < 128; k++) s += sg[tid * DD + k];
        out_loss[b0 + tid] = s * (1.0f / T_STEPS);
    }
    __syncthreads();

    // --- predictions = relu(h @ Wd + bd) @ Wo + bo ---
    float p0a = bd[j], p1a = bd[j];
    for (int k = 0; k < 128; k++) {
        float w = Wd[k * DD + j];
        p0a = fmaf(sh[r0 * DD + k], w, p0a);
        p1a = fmaf(sh[r1 * DD + k], w, p1a);
    }
    float wo = Wo[j];
    sg[r0 * DD + j] = fmaxf(p0a, 0.0f) * wo;
    sg[r1 * DD + j] = fmaxf(p1a, 0.0f) * wo;
    __syncthreads();
    if (tid < 4) {
        float s = 0.0f;
        for (int k = 0; k < 128; k++) s += sg[tid * DD + k];
        out_pred[b0 + tid] = s + bo[0];
    }
}

// ---------------------------------------------------------------------------
extern "C" void kernel_launch(void* const* d_in, const int* in_sizes, int n_in,
                              void* d_out, int out_size)
{
    const float* values = (const float*)d_in[0];
    const float* masks  = (const float*)d_in[1];
    const float* deltas = (const float*)d_in[2];
    const float* Wth    = (const float*)d_in[3];
    const float* bth    = (const float*)d_in[4];
    const float* Wtx    = (const float*)d_in[5];
    const float* btx    = (const float*)d_in[6];
    const float* Whr    = (const float*)d_in[7];
    const float* bhr    = (const float*)d_in[8];
    const float* Wfr    = (const float*)d_in[9];
    const float* bfr    = (const float*)d_in[10];
    const float* Wwc    = (const float*)d_in[11];
    const float* bwc    = (const float*)d_in[12];
    const float* Wk     = (const float*)d_in[13];
    const float* Wr     = (const float*)d_in[14];
    const float* bl     = (const float*)d_in[15];
    const float* Wd     = (const float*)d_in[16];
    const float* bd     = (const float*)d_in[17];
    const float* Wo     = (const float*)d_in[18];
    const float* bo     = (const float*)d_in[19];

    float *pGh, *pGx, *pBeta, *pGm, *pDen, *pWthT, *pWtxT, *pWhrP, *pWfrP, *pWgP;
    cudaGetSymbolAddress((void**)&pGh,   g_Gh);
    cudaGetSymbolAddress((void**)&pGx,   g_Gx);
    cudaGetSymbolAddress((void**)&pBeta, g_Beta);
    cudaGetSymbolAddress((void**)&pGm,   g_Gm);
    cudaGetSymbolAddress((void**)&pDen,  g_den);
    cudaGetSymbolAddress((void**)&pWthT, g_WthT);
    cudaGetSymbolAddress((void**)&pWtxT, g_WtxT);
    cudaGetSymbolAddress((void**)&pWhrP, g_WhrP);
    cudaGetSymbolAddress((void**)&pWfrP, g_WfrP);
    cudaGetSymbolAddress((void**)&pWgP,  g_WgP);

    prep_weights<<<512, 256>>>(Wth, Wtx, Whr, Wfr, Wk, Wr,
                               pWthT, pWtxT, pWhrP, pWfrP, pWgP);
    denom_kernel<<<128, 256>>>(masks, pDen);

    dim3 g1(1024, 2);
    sgemm_epi<<<g1, 256>>>(deltas, nullptr, pWthT, bth, pGh, 128, 128, 0);
    sgemm_epi<<<g1, 256>>>(deltas, nullptr, pWtxT, btx, pGx, 128, 128, 0);
    sgemm_epi<<<g1, 256>>>(pGx, masks, Wwc, bwc, pBeta, 128, 256, 1);
    dim3 g2(1024, 8);
    sgemm_epi<<<g2, 256>>>(masks, nullptr, Wk + 128 * 512, bl, pGm, 512, 128, 1);

    float* out = (float*)d_out;
    const size_t SMEM = (size_t)(16384 + 16384 + 512 * 4 + 2048 + 256) * sizeof(float);
    cudaFuncSetAttribute(seq_kernel, cudaFuncAttributeMaxDynamicSharedMemorySize, (int)SMEM);
    seq_kernel<<<128, 256, SMEM>>>(values, masks, pWhrP, bhr, bfr, pWfrP,
                                   pGh, pBeta, pGm, pDen,
                                   Wd, bd, Wo, bo, pWgP,
                                   out,                     // predictions [512]
                                   out + 512,               // imputations [512*128*128]
                                   out + 512 + 8388608);    // custom_loss [512]
}

// round 4
// speedup vs baseline: 1.2275x; 1.1336x over previous
#include <cuda_runtime.h>
#include <cuda_bf16.h>
#include <math.h>

// ---------------------------------------------------------------------------
// RITS / BRITS-style recurrent imputation. B=512, T=128, D=H=128.
// Launch order: prep(+denom), sgemm x4, seq  -> seq is launch #5 (ncu -s5).
// ---------------------------------------------------------------------------

#define T_STEPS  128
#define DD       128

typedef unsigned long long ull;

// Scratch (device globals; no runtime allocation allowed)
__device__ __align__(16) float g_Gh[8388608];     // [BT, 128]
__device__ __align__(16) float g_Gx[8388608];     // [BT, 128]
__device__ __align__(16) float g_Beta[8388608];   // [BT, 128]
__device__ __align__(16) float g_Gm[33554432];    // [BT, 512]
__device__ __align__(16) float g_den[128];
__device__ __align__(16) float g_WthT[16384];
__device__ __align__(16) float g_WtxT[16384];
__device__ __align__(16) float g_WhrQ[16384];     // [32 k4][128 j][4 e]
__device__ __align__(16) float g_WfrQ[16384];     // [32 k4][128 j][4 e]
__device__ __align__(16) float g_WgQ[131072];     // [64 k4][512 n][4 e]

__device__ __forceinline__ float sigmoidf_(float x) { return 1.0f / (1.0f + expf(-x)); }

__device__ __forceinline__ void ffma2(ull& d, ull a, ull b) {
    asm("fma.rn.f32x2 %0, %1, %2, %0;" : "+l"(d) : "l"(a), "l"(b));
}
__device__ __forceinline__ ull packf2(float a, float b) {
    ull u; asm("mov.b64 %0, {%1, %2};" : "=l"(u) : "f"(a), "f"(b)); return u;
}
__device__ __forceinline__ float hsum2(ull u) {
    float x, y; asm("mov.b64 {%0, %1}, %2;" : "=f"(x), "=f"(y) : "l"(u));
    return x + y;
}

// ---------------------------------------------------------------------------
// Prep: transposes + quad-k repacks + denom (blocks < 128 do denom for t=bid)
// ---------------------------------------------------------------------------
__global__ void prep_weights(const float* __restrict__ Wth, const float* __restrict__ Wtx,
                             const float* __restrict__ Whr, const float* __restrict__ Wfr,
                             const float* __restrict__ Wk,  const float* __restrict__ Wr,
                             const float* __restrict__ masks,
                             float* __restrict__ WthT, float* __restrict__ WtxT,
                             float* __restrict__ WhrQ, float* __restrict__ WfrQ,
                             float* __restrict__ WgQ,  float* __restrict__ den)
{
    int idx = blockIdx.x * blockDim.x + threadIdx.x;
    if (idx < 16384) {
        int k = idx >> 7, j = idx & 127;
        WthT[idx] = Wth[j * 128 + k];
        WtxT[idx] = Wtx[j * 128 + k];
        // quad-k: WhrQ[k4*512 + j*4 + e] = Whr[(4k4+e)*128 + j]
        int k4 = idx >> 9, rem = idx & 511, jj = rem >> 2, e = rem & 3;
        int kk = 4 * k4 + e;
        WhrQ[idx] = Whr[kk * 128 + jj];
        WfrQ[idx] = Wfr[jj * 128 + kk];     // z_hat uses Wfr[j][k]
    }
    if (idx < 131072) {
        // WgQ[k4*2048 + n*4 + e] = Wg[(4k4+e)*512 + n], Wg = [Wk_top; Wr]
        int k4 = idx >> 11, rem = idx & 2047, n = rem >> 2, e = rem & 3;
        int k = 4 * k4 + e;
        WgQ[idx] = (k < 128) ? Wk[k * 512 + n] : Wr[(k - 128) * 512 + n];
    }
    // denom: blocks 0..127 reduce masks[:, t=bid, :]
    if (blockIdx.x < 128) {
        int t = blockIdx.x;
        float s = 0.0f;
        for (int i = threadIdx.x; i < 512 * 128; i += blockDim.x) {
            int b = i >> 7, d = i & 127;
            s += masks[((size_t)b * T_STEPS + t) * DD + d];
        }
        __shared__ float red[256];
        red[threadIdx.x] = s;
        __syncthreads();
        for (int off = 128; off > 0; off >>= 1) {
            if (threadIdx.x < off) red[threadIdx.x] += red[threadIdx.x + off];
            __syncthreads();
        }
        if (threadIdx.x == 0) den[t] = red[0] + 1e-6f;
    }
}

// ---------------------------------------------------------------------------
// Tiled SGEMM: C[M,N] = epi(A[M,K] @ B[K,N] + bias)
// BM=128, BN=64, BK=16, 256 threads, 8x4 micro-tile, A transposed in SMEM.
// A split column-wise: k<128 -> A1, k>=128 -> A2 (both lda=128).
// epi==0: exp(-relu(v)), epi==1: v
// ---------------------------------------------------------------------------
__global__ void __launch_bounds__(256) sgemm_epi(
    const float* __restrict__ A1, const float* __restrict__ A2,
    const float* __restrict__ B, const float* __restrict__ bias,
    float* __restrict__ C, int N, int K, int epi)
{
    __shared__ float As[16][128];   // [kk][row]
    __shared__ float Bs[16][64];

    const int tid = threadIdx.x;
    const int bm = blockIdx.x * 128;
    const int bn = blockIdx.y * 64;

    const int lr = tid >> 1;            // 0..127 : A row
    const int lk = (tid & 1) * 8;       // 0 or 8 : A k offset
    const int bk = tid >> 4;            // 0..15  : B k
    const int bn4 = (tid & 15) * 4;     // B col

    const int ty = tid >> 4;            // 0..15 -> rows ty*8
    const int tx = tid & 15;            // cols tx*4

    float acc[8][4];
#pragma unroll
    for (int i = 0; i < 8; i++)
#pragma unroll
        for (int jj = 0; jj < 4; jj++) acc[i][jj] = 0.0f;

    for (int k0 = 0; k0 < K; k0 += 16) {
        const float* Ab;
        int kloc;
        if (k0 < 128) { Ab = A1; kloc = k0; } else { Ab = A2; kloc = k0 - 128; }
        float4 a0 = *(const float4*)&Ab[(size_t)(bm + lr) * 128 + kloc + lk];
        float4 a1 = *(const float4*)&Ab[(size_t)(bm + lr) * 128 + kloc + lk + 4];
        float4 bv = *(const float4*)&B[(size_t)(k0 + bk) * N + bn + bn4];
        As[lk + 0][lr] = a0.x; As[lk + 1][lr] = a0.y;
        As[lk + 2][lr] = a0.z; As[lk + 3][lr] = a0.w;
        As[lk + 4][lr] = a1.x; As[lk + 5][lr] = a1.y;
        As[lk + 6][lr] = a1.z; As[lk + 7][lr] = a1.w;
        *(float4*)&Bs[bk][bn4] = bv;
        __syncthreads();
#pragma unroll
        for (int kk = 0; kk < 16; kk++) {
            float4 aA = *(const float4*)&As[kk][ty * 8];
            float4 aB = *(const float4*)&As[kk][ty * 8 + 4];
            float4 b4 = *(const float4*)&Bs[kk][tx * 4];
            float ar[8] = {aA.x, aA.y, aA.z, aA.w, aB.x, aB.y, aB.z, aB.w};
#pragma unroll
            for (int i = 0; i < 8; i++) {
                acc[i][0] = fmaf(ar[i], b4.x, acc[i][0]);
                acc[i][1] = fmaf(ar[i], b4.y, acc[i][1]);
                acc[i][2] = fmaf(ar[i], b4.z, acc[i][2]);
                acc[i][3] = fmaf(ar[i], b4.w, acc[i][3]);
            }
        }
        __syncthreads();
    }

#pragma unroll
    for (int i = 0; i < 8; i++) {
        float4 ov;
        float* o = (float*)&ov;
#pragma unroll
        for (int jj = 0; jj < 4; jj++) {
            float v = acc[i][jj] + bias[bn + tx * 4 + jj];
            if (epi == 0) v = expf(-fmaxf(v, 0.0f));
            o[jj] = v;
        }
        *(float4*)&C[(size_t)(bm + ty * 8 + i) * N + bn + tx * 4] = ov;
    }
}

// ---------------------------------------------------------------------------
// Sequential recurrence: 128 CTAs x 4 batch rows, 512 threads (16 warps).
// Quad-k packed FFMA2, LDS.128/LDG.128 operand loads.
// Thread (j = tid&127, q = tid>>7) owns element j of batch row b0+q.
// Phase E: thread tid owns gate column n = tid for all 4 rows.
// ---------------------------------------------------------------------------
__global__ void __launch_bounds__(512, 1) seq_kernel(
    const float* __restrict__ values, const float* __restrict__ masks,
    const float* __restrict__ WhrQ_g, const float* __restrict__ bhr,
    const float* __restrict__ bfr,    const float* __restrict__ WfrQ_g,
    const float* __restrict__ Gh,     const float* __restrict__ Beta,
    const float* __restrict__ Gm,     const float* __restrict__ den,
    const float* __restrict__ Wd,     const float* __restrict__ bd,
    const float* __restrict__ Wo,     const float* __restrict__ bo,
    const float* __restrict__ WgQ,
    float* __restrict__ out_pred, float* __restrict__ out_imp,
    float* __restrict__ out_loss)
{
    extern __shared__ float sm[];
    float* sWhrQ = sm;                 // 16384
    float* sWfrQ = sm + 16384;         // 16384
    float* sh    = sm + 32768;         // 512
    float* sc    = sh + 512;           // 512
    float* sxc   = sc + 512;           // 512
    float* scc   = sxc + 512;          // 512
    float* sg    = scc + 512;          // 2048
    float* sbhr  = sg + 2048;          // 128
    float* sbfr  = sbhr + 128;         // 128

    const int tid = threadIdx.x;
    const int b0 = blockIdx.x * 4;

    for (int i = tid; i < 16384; i += 512) { sWhrQ[i] = WhrQ_g[i]; sWfrQ[i] = WfrQ_g[i]; }
    if (tid < 128) { sbhr[tid] = bhr[tid]; sbfr[tid] = bfr[tid]; }
    if (tid < 512) { sh[tid] = 0.0f; sc[tid] = 0.0f; }
    __syncthreads();

    const int j = tid & 127;
    const int q = tid >> 7;                       // 0..3
    const size_t rowbase = (size_t)(b0 + q) * T_STEPS;

    float lsum = 0.0f;

    // Prefetch t=0 per-element operands
    float cx = values[rowbase * DD + j];
    float cm = masks[rowbase * DD + j];
    float cg = Gh[rowbase * DD + j];
    float cb = Beta[rowbase * DD + j];
    float cden = den[0];

    const float* wq = WgQ + (size_t)tid * 4;

    for (int t = 0; t < T_STEPS; t++) {
        const size_t bt = rowbase + t;

        // --- Phase A: decay h ---
        float x = cx, m = cm;
        float h = sh[q * DD + j] * cg;
        sh[q * DD + j] = h;
        float rd = 1.0f / cden;
        float be = cb;
        __syncthreads();                                   // S1

        // --- Prefetch next step + Gm(t) for Phase E ---
        {
            int tn = (t + 1 < T_STEPS) ? (t + 1) : (T_STEPS - 1);
            size_t nb = rowbase + tn;
            cx = values[nb * DD + j];
            cm = masks[nb * DD + j];
            cg = Gh[nb * DD + j];
            cb = Beta[nb * DD + j];
            cden = den[tn];
        }
        float gm[4];
#pragma unroll
        for (int r = 0; r < 4; r++)
            gm[r] = Gm[((size_t)(b0 + r) * T_STEPS + t) * 512 + tid];

        // --- Phase B: x_hat = h @ Whr + bhr ---
        ull a = packf2(sbhr[j], 0.0f);
#pragma unroll 8
        for (int k4 = 0; k4 < 32; k4++) {
            ulonglong2 w = *(const ulonglong2*)&sWhrQ[k4 * 512 + j * 4];
            ulonglong2 v = *(const ulonglong2*)&sh[q * DD + k4 * 4];
            ffma2(a, v.x, w.x);
            ffma2(a, v.y, w.y);
        }
        float xh = hsum2(a);
        float xc = m * x + (1.0f - m) * xh;
        sxc[q * DD + j] = xc;
        lsum += fabsf(x - xh) * m * rd;
        __syncthreads();                                   // S2

        // --- Phase C: z_hat = x_c @ Wfr^T + bfr ---
        a = packf2(sbfr[j], 0.0f);
#pragma unroll 8
        for (int k4 = 0; k4 < 32; k4++) {
            ulonglong2 w = *(const ulonglong2*)&sWfrQ[k4 * 512 + j * 4];
            ulonglong2 v = *(const ulonglong2*)&sxc[q * DD + k4 * 4];
            ffma2(a, v.x, w.x);
            ffma2(a, v.y, w.y);
        }
        float zh = hsum2(a);
        lsum += fabsf(x - zh) * m * rd;

        // --- Phase D: c_hat / c_c / imputation ---
        float ch = be * zh + (1.0f - be) * xh;
        lsum += fabsf(x - ch) * m * rd;
        float cc = m * x + (1.0f - m) * ch;
        scc[q * DD + j] = cc;
        out_imp[bt * DD + j] = cc;
        __syncthreads();                                   // S3

        // --- Phase E: gates[n=tid] = Gm + cc @ Wg[0:128] + h @ Wg[128:256] ---
        ull acc0 = packf2(gm[0], 0.0f);
        ull acc1 = packf2(gm[1], 0.0f);
        ull acc2 = packf2(gm[2], 0.0f);
        ull acc3 = packf2(gm[3], 0.0f);
#pragma unroll 4
        for (int k4 = 0; k4 < 32; k4++) {
            ulonglong2 w = *(const ulonglong2*)&wq[(size_t)k4 * 2048];
            ulonglong2 v0 = *(const ulonglong2*)&scc[0 * DD + k4 * 4];
            ulonglong2 v1 = *(const ulonglong2*)&scc[1 * DD + k4 * 4];
            ulonglong2 v2 = *(const ulonglong2*)&scc[2 * DD + k4 * 4];
            ulonglong2 v3 = *(const ulonglong2*)&scc[3 * DD + k4 * 4];
            ffma2(acc0, v0.x, w.x); ffma2(acc0, v0.y, w.y);
            ffma2(acc1, v1.x, w.x); ffma2(acc1, v1.y, w.y);
            ffma2(acc2, v2.x, w.x); ffma2(acc2, v2.y, w.y);
            ffma2(acc3, v3.x, w.x); ffma2(acc3, v3.y, w.y);
        }
#pragma unroll 4
        for (int k4 = 32; k4 < 64; k4++) {
            ulonglong2 w = *(const ulonglong2*)&wq[(size_t)k4 * 2048];
            int ko = (k4 - 32) * 4;
            ulonglong2 v0 = *(const ulonglong2*)&sh[0 * DD + ko];
            ulonglong2 v1 = *(const ulonglong2*)&sh[1 * DD + ko];
            ulonglong2 v2 = *(const ulonglong2*)&sh[2 * DD + ko];
            ulonglong2 v3 = *(const ulonglong2*)&sh[3 * DD + ko];
            ffma2(acc0, v0.x, w.x); ffma2(acc0, v0.y, w.y);
            ffma2(acc1, v1.x, w.x); ffma2(acc1, v1.y, w.y);
            ffma2(acc2, v2.x, w.x); ffma2(acc2, v2.y, w.y);
            ffma2(acc3, v3.x, w.x); ffma2(acc3, v3.y, w.y);
        }
        sg[0 * 512 + tid] = hsum2(acc0);
        sg[1 * 512 + tid] = hsum2(acc1);
        sg[2 * 512 + tid] = hsum2(acc2);
        sg[3 * 512 + tid] = hsum2(acc3);
        __syncthreads();                                   // S4

        // --- Phase F: LSTM cell update (i, f, g, o), element (q, j) ---
        {
            float gi = sg[q * 512 + j];
            float gf = sg[q * 512 + 128 + j];
            float gg = sg[q * 512 + 256 + j];
            float go = sg[q * 512 + 384 + j];
            float cn = sigmoidf_(gf) * sc[q * DD + j] + sigmoidf_(gi) * tanhf(gg);
            sc[q * DD + j] = cn;
            sh[q * DD + j] = sigmoidf_(go) * tanhf(cn);
        }
        // no extra sync: next-iter S1 orders sh writes before cross-thread reads
    }

    __syncthreads();

    // --- custom_loss: mean over T (per-step /denom already applied) ---
    sg[q * DD + j] = lsum;
    __syncthreads();
    if (tid < 4) {
        float s = 0.0f;
        for (int k = 0; k < 128; k++) s += sg[tid * DD + k];
        out_loss[b0 + tid] = s * (1.0f / T_STEPS);
    }
    __syncthreads();

    // --- predictions = relu(h @ Wd + bd) @ Wo + bo ---
    float pa = bd[j];
    for (int k = 0; k < 128; k++) {
        pa = fmaf(sh[q * DD + k], Wd[k * DD + j], pa);
    }
    sg[q * DD + j] = fmaxf(pa, 0.0f) * Wo[j];
    __syncthreads();
    if (tid < 4) {
        float s = 0.0f;
        for (int k = 0; k < 128; k++) s += sg[tid * DD + k];
        out_pred[b0 + tid] = s + bo[0];
    }
}

// ---------------------------------------------------------------------------
extern "C" void kernel_launch(void* const* d_in, const int* in_sizes, int n_in,
                              void* d_out, int out_size)
{
    const float* values = (const float*)d_in[0];
    const float* masks  = (const float*)d_in[1];
    const float* deltas = (const float*)d_in[2];
    const float* Wth    = (const float*)d_in[3];
    const float* bth    = (const float*)d_in[4];
    const float* Wtx    = (const float*)d_in[5];
    const float* btx    = (const float*)d_in[6];
    const float* Whr    = (const float*)d_in[7];
    const float* bhr    = (const float*)d_in[8];
    const float* Wfr    = (const float*)d_in[9];
    const float* bfr    = (const float*)d_in[10];
    const float* Wwc    = (const float*)d_in[11];
    const float* bwc    = (const float*)d_in[12];
    const float* Wk     = (const float*)d_in[13];
    const float* Wr     = (const float*)d_in[14];
    const float* bl     = (const float*)d_in[15];
    const float* Wd     = (const float*)d_in[16];
    const float* bd     = (const float*)d_in[17];
    const float* Wo     = (const float*)d_in[18];
    const float* bo     = (const float*)d_in[19];

    float *pGh, *pGx, *pBeta, *pGm, *pDen, *pWthT, *pWtxT, *pWhrQ, *pWfrQ, *pWgQ;
    cudaGetSymbolAddress((void**)&pGh,   g_Gh);
    cudaGetSymbolAddress((void**)&pGx,   g_Gx);
    cudaGetSymbolAddress((void**)&pBeta, g_Beta);
    cudaGetSymbolAddress((void**)&pGm,   g_Gm);
    cudaGetSymbolAddress((void**)&pDen,  g_den);
    cudaGetSymbolAddress((void**)&pWthT, g_WthT);
    cudaGetSymbolAddress((void**)&pWtxT, g_WtxT);
    cudaGetSymbolAddress((void**)&pWhrQ, g_WhrQ);
    cudaGetSymbolAddress((void**)&pWfrQ, g_WfrQ);
    cudaGetSymbolAddress((void**)&pWgQ,  g_WgQ);

    // Launch 0: prep (incl. denom)
    prep_weights<<<512, 256>>>(Wth, Wtx, Whr, Wfr, Wk, Wr, masks,
                               pWthT, pWtxT, pWhrQ, pWfrQ, pWgQ, pDen);

    // Launches 1-4: GEMMs
    dim3 g1(512, 2);
    sgemm_epi<<<g1, 256>>>(deltas, nullptr, pWthT, bth, pGh, 128, 128, 0);
    sgemm_epi<<<g1, 256>>>(deltas, nullptr, pWtxT, btx, pGx, 128, 128, 0);
    sgemm_epi<<<g1, 256>>>(pGx, masks, Wwc, bwc, pBeta, 128, 256, 1);
    dim3 g2(512, 8);
    sgemm_epi<<<g2, 256>>>(masks, nullptr, Wk + 128 * 512, bl, pGm, 512, 128, 1);

    // Launch 5: sequential recurrence (profiled by ncu -s5 -c1)
    float* out = (float*)d_out;
    const size_t SMEM = (size_t)(16384 + 16384 + 512 * 4 + 2048 + 256) * sizeof(float);
    cudaFuncSetAttribute(seq_kernel, cudaFuncAttributeMaxDynamicSharedMemorySize, (int)SMEM);
    seq_kernel<<<128, 512, SMEM>>>(values, masks, pWhrQ, bhr, bfr, pWfrQ,
                                   pGh, pBeta, pGm, pDen,
                                   Wd, bd, Wo, bo, pWgQ,
                                   out,                     // predictions [512]
                                   out + 512,               // imputations [512*128*128]
                                   out + 512 + 8388608);    // custom_loss [512]
}